// round 7
// baseline (speedup 1.0000x reference)
#include <cuda_runtime.h>
#include <cuda_bf16.h>

// Fused CrossEntropy + (LUT-remapped) BCE loss — single launch, 4 rows/thread.
//
// loss = ( sum_i (lse(pred_i) - pred_i[tgt_i]) + 100 * n_mismatch ) / N
// where mismatch_i = [ (argmax(pred_i) in [2,7]) != (tgt_i in [2,7]) ].
//
// R7 vs R6: 4 rows per thread. 10x LDG.128 (pred) + 1x LDG.128 (targets)
// front-batched -> MLP_p1 ~11 (was 6), halving exposed DRAM latency per the
// 3-term LDG model. Profile R6 showed DRAM 46.5% / issue 35% = latency-bound.

__device__ double g_acc = 0.0;
__device__ unsigned int g_count = 0u;

#define LOG2E 1.4426950408889634f
#define LN2   0.6931471805599453f

__device__ __forceinline__ float row_loss(
    float v0, float v1, float v2, float v3, float v4,
    float v5, float v6, float v7, float v8, float v9, int tgt)
{
    tgt = (tgt < 0) ? 0 : ((tgt > 9) ? 9 : tgt);

    // group maxes (FMNMX)
    const float m01 = fmaxf(v0, v1);
    const float m27 = fmaxf(fmaxf(fmaxf(v2, v3), fmaxf(v4, v5)), fmaxf(v6, v7));
    const float m89 = fmaxf(v8, v9);
    const float m = fmaxf(fmaxf(m01, m27), m89);

    // b_pred without argmax (exact under first-occurrence ties:
    // indices 0,1 < 2..7 < 8,9)
    const int bp = (m27 > m01) & (m27 >= m89);
    const int bt = (tgt >= 2) & (tgt <= 7);

    // sum exp2(v*log2e - m*log2e): FFMA + EX2 each
    const float mc = m * LOG2E;
    float s;
    s  = exp2f(fmaf(v0, LOG2E, -mc));
    s += exp2f(fmaf(v1, LOG2E, -mc));
    s += exp2f(fmaf(v2, LOG2E, -mc));
    s += exp2f(fmaf(v3, LOG2E, -mc));
    s += exp2f(fmaf(v4, LOG2E, -mc));
    s += exp2f(fmaf(v5, LOG2E, -mc));
    s += exp2f(fmaf(v6, LOG2E, -mc));
    s += exp2f(fmaf(v7, LOG2E, -mc));
    s += exp2f(fmaf(v8, LOG2E, -mc));
    s += exp2f(fmaf(v9, LOG2E, -mc));

    const float lse = fmaf(__log2f(s), LN2, m);

    // v[tgt] via register select chain (no local memory)
    float vt = v0;
    vt = (tgt == 1) ? v1 : vt;
    vt = (tgt == 2) ? v2 : vt;
    vt = (tgt == 3) ? v3 : vt;
    vt = (tgt == 4) ? v4 : vt;
    vt = (tgt == 5) ? v5 : vt;
    vt = (tgt == 6) ? v6 : vt;
    vt = (tgt == 7) ? v7 : vt;
    vt = (tgt == 8) ? v8 : vt;
    vt = (tgt == 9) ? v9 : vt;

    return (lse - vt) + ((bp != bt) ? 100.0f : 0.0f);
}

__global__ void __launch_bounds__(256) loss_kernel(
    const float* __restrict__ pred,
    const int* __restrict__ target,
    float* __restrict__ out,
    int n_rows)
{
    const int i  = blockIdx.x * blockDim.x + threadIdx.x;  // quad index
    const int r0 = 4 * i;

    float local = 0.0f;
    if (r0 + 3 < n_rows) {
        // 4 rows: 160 bytes at byte offset 160*i -> 16B aligned.
        const float4* __restrict__ p =
            reinterpret_cast<const float4*>(pred + (size_t)i * 40);
        // Front-batched loads: MLP_p1 = 11
        const float4 q0 = p[0];
        const float4 q1 = p[1];
        const float4 q2 = p[2];
        const float4 q3 = p[3];
        const float4 q4 = p[4];
        const float4 q5 = p[5];
        const float4 q6 = p[6];
        const float4 q7 = p[7];
        const float4 q8 = p[8];
        const float4 q9 = p[9];
        const int4 t4 = *reinterpret_cast<const int4*>(target + (size_t)4 * i);

        local  = row_loss(q0.x, q0.y, q0.z, q0.w,
                          q1.x, q1.y, q1.z, q1.w,
                          q2.x, q2.y, t4.x);
        local += row_loss(q2.z, q2.w,
                          q3.x, q3.y, q3.z, q3.w,
                          q4.x, q4.y, q4.z, q4.w, t4.y);
        local += row_loss(q5.x, q5.y, q5.z, q5.w,
                          q6.x, q6.y, q6.z, q6.w,
                          q7.x, q7.y, t4.z);
        local += row_loss(q7.z, q7.w,
                          q8.x, q8.y, q8.z, q8.w,
                          q9.x, q9.y, q9.z, q9.w, t4.w);
    } else if (r0 < n_rows) {
        // tail: per-row scalar-safe path (float2 loads, 8B aligned)
        for (int r = r0; r < n_rows; r++) {
            const float2* __restrict__ p =
                reinterpret_cast<const float2*>(pred + (size_t)r * 10);
            const float2 a0 = p[0];
            const float2 a1 = p[1];
            const float2 a2 = p[2];
            const float2 a3 = p[3];
            const float2 a4 = p[4];
            local += row_loss(a0.x, a0.y, a1.x, a1.y, a2.x,
                              a2.y, a3.x, a3.y, a4.x, a4.y, target[r]);
        }
    }

    // --- block reduction: warp shuffle -> shared -> one double red ---
    __shared__ float warp_sums[8];  // 256 threads = 8 warps

#pragma unroll
    for (int off = 16; off > 0; off >>= 1)
        local += __shfl_down_sync(0xFFFFFFFFu, local, off);

    const int lane = threadIdx.x & 31;
    const int wid  = threadIdx.x >> 5;
    if (lane == 0) warp_sums[wid] = local;
    __syncthreads();

    __shared__ bool is_last;
    if (wid == 0) {
        float blk = (lane < 8) ? warp_sums[lane] : 0.0f;
#pragma unroll
        for (int off = 4; off > 0; off >>= 1)
            blk += __shfl_down_sync(0xFFFFFFFFu, blk, off);
        if (lane == 0) {
            const double dblk = (double)blk;
            asm volatile("red.release.gpu.global.add.f64 [%0], %1;"
                         :: "l"(&g_acc), "d"(dblk) : "memory");
            unsigned int done;
            unsigned int one = 1u;
            asm volatile("atom.acq_rel.gpu.global.add.u32 %0, [%1], %2;"
                         : "=r"(done) : "l"(&g_count), "r"(one) : "memory");
            is_last = (done == gridDim.x - 1u);
        }
    }
    __syncthreads();

    // Last block finalizes: write output, reset state for next replay.
    if (is_last && threadIdx.x == 0) {
        double acc;
        asm volatile("ld.acquire.gpu.global.f64 %0, [%1];"
                     : "=d"(acc) : "l"(&g_acc) : "memory");
        out[0] = (float)(acc / (double)n_rows);
        g_acc = 0.0;
        g_count = 0u;
    }
}

extern "C" void kernel_launch(void* const* d_in, const int* in_sizes, int n_in,
                              void* d_out, int out_size) {
    const float* pred   = (const float*)d_in[0];
    const int*   target = (const int*)d_in[1];
    float*       out    = (float*)d_out;

    const int n_rows  = in_sizes[1];  // target element count = N
    const int n_quads = (n_rows + 3) / 4;

    const int threads = 256;
    const int blocks = (n_quads + threads - 1) / threads;
    loss_kernel<<<blocks, threads>>>(pred, target, out, n_rows);
}

// round 10
// speedup vs baseline: 1.2312x; 1.2312x over previous
#include <cuda_runtime.h>
#include <cuda_bf16.h>
#include <cstdint>

// Fused CrossEntropy + (LUT-remapped) BCE loss — single launch,
// coalesced smem staging.
//
// loss = ( sum_i (lse(pred_i) - pred_i[tgt_i]) + 100 * n_mismatch ) / N
// where mismatch_i = [ (argmax(pred_i) in [2,7]) != (tgt_i in [2,7]) ].
//
// Direct row loads had lane stride 80B -> each warp LDG.128 touched 20 cache
// lines (nL=20) -> ~5x the L1tex wavefront floor, the real binder (DRAM stuck
// <50%). Now each block stages 512 rows via coalesced cp.async.cg (nL=4,
// optimal), then reads rows from smem with LDS.128 at 80B stride —
// conflict-free (5 coprime 8: each 8-lane phase hits a permutation of bank
// groups).

__device__ double g_acc = 0.0;
__device__ unsigned int g_count = 0u;

#define LOG2E 1.4426950408889634f
#define LN2   0.6931471805599453f

constexpr int THREADS = 256;
constexpr int ROWS_PER_BLOCK = 2 * THREADS;                 // 512
constexpr int UNITS_PER_BLOCK = ROWS_PER_BLOCK * 40 / 16;   // 1280 float4s

__device__ __forceinline__ float row_loss(
    float v0, float v1, float v2, float v3, float v4,
    float v5, float v6, float v7, float v8, float v9, int tgt)
{
    tgt = (tgt < 0) ? 0 : ((tgt > 9) ? 9 : tgt);

    // group maxes (FMNMX)
    const float m01 = fmaxf(v0, v1);
    const float m27 = fmaxf(fmaxf(fmaxf(v2, v3), fmaxf(v4, v5)), fmaxf(v6, v7));
    const float m89 = fmaxf(v8, v9);
    const float m = fmaxf(fmaxf(m01, m27), m89);

    // b_pred without argmax (exact under first-occurrence ties)
    const int bp = (m27 > m01) & (m27 >= m89);
    const int bt = (tgt >= 2) & (tgt <= 7);

    // sum exp2(v*log2e - m*log2e): FFMA + EX2 each
    const float mc = m * LOG2E;
    float s;
    s  = exp2f(fmaf(v0, LOG2E, -mc));
    s += exp2f(fmaf(v1, LOG2E, -mc));
    s += exp2f(fmaf(v2, LOG2E, -mc));
    s += exp2f(fmaf(v3, LOG2E, -mc));
    s += exp2f(fmaf(v4, LOG2E, -mc));
    s += exp2f(fmaf(v5, LOG2E, -mc));
    s += exp2f(fmaf(v6, LOG2E, -mc));
    s += exp2f(fmaf(v7, LOG2E, -mc));
    s += exp2f(fmaf(v8, LOG2E, -mc));
    s += exp2f(fmaf(v9, LOG2E, -mc));

    const float lse = fmaf(__log2f(s), LN2, m);

    // v[tgt] via register select chain (no local memory)
    float vt = v0;
    vt = (tgt == 1) ? v1 : vt;
    vt = (tgt == 2) ? v2 : vt;
    vt = (tgt == 3) ? v3 : vt;
    vt = (tgt == 4) ? v4 : vt;
    vt = (tgt == 5) ? v5 : vt;
    vt = (tgt == 6) ? v6 : vt;
    vt = (tgt == 7) ? v7 : vt;
    vt = (tgt == 8) ? v8 : vt;
    vt = (tgt == 9) ? v9 : vt;

    return (lse - vt) + ((bp != bt) ? 100.0f : 0.0f);
}

__global__ void __launch_bounds__(THREADS) loss_kernel(
    const float* __restrict__ pred,
    const int* __restrict__ target,
    float* __restrict__ out,
    int n_rows)
{
    __shared__ float4 s_pred[UNITS_PER_BLOCK];  // 20480 B
    __shared__ float warp_sums[8];

    const int tid = threadIdx.x;

    // ---- stage pred tile: coalesced cp.async.cg, 5 x 16B per thread ----
    const long long block_unit_base = (long long)blockIdx.x * UNITS_PER_BLOCK;
    const long long full_units = ((long long)n_rows * 40) >> 4;  // whole 16B units
    const float4* __restrict__ gp = reinterpret_cast<const float4*>(pred);
    const unsigned int s_base =
        (unsigned int)__cvta_generic_to_shared(s_pred);

#pragma unroll
    for (int k = 0; k < 5; k++) {
        const long long u = block_unit_base + tid + k * THREADS;
        const unsigned int saddr =
            s_base + (unsigned int)(tid + k * THREADS) * 16u;
        if (u < full_units) {
            asm volatile("cp.async.cg.shared.global [%0], [%1], 16;"
                         :: "r"(saddr), "l"(gp + u));
        }
    }
    asm volatile("cp.async.commit_group;");

    // ---- targets in parallel with the staging copy ----
    const int pair = blockIdx.x * THREADS + tid;  // pair index
    const int r0 = 2 * pair;
    int t0 = 0, t1 = 0;
    const bool full_pair = (r0 + 1 < n_rows);
    const bool has_row   = (r0 < n_rows);
    if (full_pair) {
        const int2 tt = *reinterpret_cast<const int2*>(target + (size_t)2 * pair);
        t0 = tt.x; t1 = tt.y;
    } else if (has_row) {
        t0 = target[r0];
    }

    asm volatile("cp.async.wait_group 0;" ::: "memory");
    __syncthreads();

    // ---- compute from smem: 5 x LDS.128 at 80B stride (conflict-free) ----
    float local = 0.0f;
    if (full_pair) {
        const float4* __restrict__ sp = s_pred + tid * 5;
        const float4 q0 = sp[0];
        const float4 q1 = sp[1];
        const float4 q2 = sp[2];
        const float4 q3 = sp[3];
        const float4 q4 = sp[4];

        local = row_loss(q0.x, q0.y, q0.z, q0.w,
                         q1.x, q1.y, q1.z, q1.w,
                         q2.x, q2.y, t0)
              + row_loss(q2.z, q2.w,
                         q3.x, q3.y, q3.z, q3.w,
                         q4.x, q4.y, q4.z, q4.w, t1);
    } else if (has_row) {
        // odd-N tail row: read directly from global (smem may miss last 8B)
        const float2* __restrict__ p =
            reinterpret_cast<const float2*>(pred + (size_t)r0 * 10);
        const float2 a0 = p[0];
        const float2 a1 = p[1];
        const float2 a2 = p[2];
        const float2 a3 = p[3];
        const float2 a4 = p[4];
        local = row_loss(a0.x, a0.y, a1.x, a1.y, a2.x,
                         a2.y, a3.x, a3.y, a4.x, a4.y, t0);
    }

    // ---- block reduction: warp shuffle -> shared -> one double red ----
#pragma unroll
    for (int off = 16; off > 0; off >>= 1)
        local += __shfl_down_sync(0xFFFFFFFFu, local, off);

    const int lane = tid & 31;
    const int wid  = tid >> 5;
    if (lane == 0) warp_sums[wid] = local;
    __syncthreads();

    __shared__ bool is_last;
    if (wid == 0) {
        float blk = (lane < 8) ? warp_sums[lane] : 0.0f;
#pragma unroll
        for (int off = 4; off > 0; off >>= 1)
            blk += __shfl_down_sync(0xFFFFFFFFu, blk, off);
        if (lane == 0) {
            const double dblk = (double)blk;
            asm volatile("red.release.gpu.global.add.f64 [%0], %1;"
                         :: "l"(&g_acc), "d"(dblk) : "memory");
            unsigned int done;
            unsigned int one = 1u;
            asm volatile("atom.acq_rel.gpu.global.add.u32 %0, [%1], %2;"
                         : "=r"(done) : "l"(&g_count), "r"(one) : "memory");
            is_last = (done == gridDim.x - 1u);
        }
    }
    __syncthreads();

    // Last block finalizes: write output, reset state for next replay.
    if (is_last && tid == 0) {
        double acc;
        asm volatile("ld.acquire.gpu.global.f64 %0, [%1];"
                     : "=d"(acc) : "l"(&g_acc) : "memory");
        out[0] = (float)(acc / (double)n_rows);
        g_acc = 0.0;
        g_count = 0u;
    }
}

extern "C" void kernel_launch(void* const* d_in, const int* in_sizes, int n_in,
                              void* d_out, int out_size) {
    const float* pred   = (const float*)d_in[0];
    const int*   target = (const int*)d_in[1];
    float*       out    = (float*)d_out;

    const int n_rows  = in_sizes[1];  // target element count = N
    const int n_pairs = (n_rows + 1) / 2;
    const int blocks  = (n_pairs + THREADS - 1) / THREADS;

    loss_kernel<<<blocks, THREADS>>>(pred, target, out, n_rows);
}